// round 6
// baseline (speedup 1.0000x reference)
#include <cuda_runtime.h>
#include <cuda_bf16.h>

#define N_NODES 100000
#define N_EDGES 1600000
#define CH 128
#define SCAN_BS 1024
#define SCAN_BLOCKS 98   // ceil(100000/1024)

// ---------------- scratch (device globals; referenced ONLY from device code) ----------------
__device__ int   g_is64;                      // 1 if edge_index is int64, 0 if int32
__device__ int   g_deg[N_NODES];              // degree, then reused as CSR fill cursor
__device__ float g_inv[N_NODES];
__device__ int   g_rowptr[N_NODES + 1];
__device__ int   g_bsum[SCAN_BLOCKS + 1];
__device__ int   g_col[N_EDGES];              // src sorted by dst (CSR adjacency)
__device__ float g_tl[(size_t)N_NODES * CH];  // A @ Wl
__device__ float g_tr[(size_t)N_NODES * CH];  // A @ Wr + b
__device__ float g_h [(size_t)N_NODES * CH];  // hidden layer output

// ---------------- dtype detection ----------------
// int64 little-endian with values < 2^31 => every odd 32-bit word is 0.
// int32 => odd words are random node ids; P(all 128 == 0) ~ 0.
__global__ void detect_dtype_kernel(const int* __restrict__ ei32) {
    if (threadIdx.x == 0) {
        int odd_nonzero = 0;
        for (int i = 0; i < 128; i++)
            if (ei32[2 * i + 1] != 0) odd_nonzero++;
        g_is64 = (odd_nonzero == 0) ? 1 : 0;
    }
}

__device__ __forceinline__ int edge_at(const void* ei, long long idx) {
    if (g_is64) return (int)((const long long*)ei)[idx];
    return ((const int*)ei)[idx];
}

// ---------------- zero degree array ----------------
__global__ void zero_deg_kernel() {
    int i = blockIdx.x * 256 + threadIdx.x;
    if (i < N_NODES) g_deg[i] = 0;
}

// ---------------- degree histogram ----------------
__global__ void count_deg_kernel(const void* __restrict__ ei) {
    int e = blockIdx.x * 256 + threadIdx.x;
    if (e < N_EDGES) {
        int d = edge_at(ei, (long long)N_EDGES + e);
        atomicAdd(&g_deg[d], 1);
    }
}

// ---------------- block-local exclusive scan ----------------
__global__ void scan_blocks_kernel() {
    __shared__ int s[SCAN_BS];
    int tid = threadIdx.x;
    int i = blockIdx.x * SCAN_BS + tid;
    int v = (i < N_NODES) ? g_deg[i] : 0;
    s[tid] = v;
    __syncthreads();
    #pragma unroll
    for (int off = 1; off < SCAN_BS; off <<= 1) {
        int x = 0;
        if (tid >= off) x = s[tid - off];
        __syncthreads();
        s[tid] += x;
        __syncthreads();
    }
    if (i < N_NODES) g_rowptr[i] = s[tid] - v;     // exclusive within block
    if (tid == SCAN_BS - 1) g_bsum[blockIdx.x] = s[SCAN_BS - 1];
}

__global__ void scan_partials_kernel() {
    if (threadIdx.x == 0) {
        int acc = 0;
        for (int b = 0; b < SCAN_BLOCKS; b++) { int t = g_bsum[b]; g_bsum[b] = acc; acc += t; }
    }
}

__global__ void finalize_kernel() {
    int i = blockIdx.x * SCAN_BS + threadIdx.x;
    if (i < N_NODES) {
        int r = g_rowptr[i] + g_bsum[blockIdx.x];
        g_rowptr[i] = r;
        int d = g_deg[i];
        g_inv[i] = 1.0f / (d > 0 ? (float)d : 1.0f);
        g_deg[i] = r;                               // becomes fill cursor
    }
    if (i == 0) g_rowptr[N_NODES] = N_EDGES;
}

// ---------------- CSR fill ----------------
__global__ void fill_csr_kernel(const void* __restrict__ ei) {
    int e = blockIdx.x * 256 + threadIdx.x;
    if (e < N_EDGES) {
        int s = edge_at(ei, e);
        int d = edge_at(ei, (long long)N_EDGES + e);
        int p = atomicAdd(&g_deg[d], 1);
        g_col[p] = s;
    }
}

// ---------------- dual GEMM: g_tl = A@Wl, g_tr = A@Wr + b ----------------
// use_h: 0 -> A = Aext (harness input), 1 -> A = g_h (hidden layer)
// blockIdx.y: 0 -> (Wl, g_tl, no bias), 1 -> (Wr, g_tr, +bias)
// Block tile M=128, N=128 (full), K chunked by 32. Thread microtile 8x8,
// rows strided by 16 (m = ty + 16*i) so shared loads stay conflict-free.
__global__ void __launch_bounds__(256, 2)
gemm_dual_kernel(const float* __restrict__ Aext, int use_h,
                 const float* __restrict__ Wl, const float* __restrict__ Wr,
                 const float* __restrict__ bias) {
    const float* A  = use_h ? g_h : Aext;
    const float* W  = blockIdx.y ? Wr   : Wl;
    float*      out = blockIdx.y ? g_tr : g_tl;

    __shared__ float sA[128][36];   // stride 36: float4-aligned, bank-safe for strided rows
    __shared__ float sW[32][128];

    int tid = threadIdx.x;
    int tx = tid & 15;      // column group: cols tx*8 .. tx*8+7
    int ty = tid >> 4;      // row base:    rows ty + 16*i
    int m0 = blockIdx.x * 128;

    float acc[8][8];
    #pragma unroll
    for (int i = 0; i < 8; i++)
        #pragma unroll
        for (int j = 0; j < 8; j++) acc[i][j] = 0.0f;

    for (int k0 = 0; k0 < CH; k0 += 32) {
        // A tile chunk: 128 rows x 32 k (1024 float4, 4 per thread)
        #pragma unroll
        for (int i = 0; i < 4; i++) {
            int lin = tid + i * 256;
            int row = lin >> 3;            // 8 float4 per row
            int kq  = (lin & 7) * 4;
            float4 v = make_float4(0.f, 0.f, 0.f, 0.f);
            int gm = m0 + row;
            if (gm < N_NODES)
                v = *(const float4*)&A[(size_t)gm * CH + k0 + kq];
            *(float4*)&sA[row][kq] = v;
        }
        // W chunk: 32 k-rows x 128 n
        #pragma unroll
        for (int i = 0; i < 4; i++) {
            int lin = tid + i * 256;
            int row = lin >> 5;            // 32 float4 per row
            int nq  = (lin & 31) * 4;
            *(float4*)&sW[row][nq] = *(const float4*)&W[(size_t)(k0 + row) * CH + nq];
        }
        __syncthreads();

        #pragma unroll
        for (int k = 0; k < 32; k++) {
            float a[8], b[8];
            #pragma unroll
            for (int i = 0; i < 8; i++) a[i] = sA[ty + 16 * i][k];
            float4 b0 = *(float4*)&sW[k][tx * 8];
            float4 b1 = *(float4*)&sW[k][tx * 8 + 4];
            b[0] = b0.x; b[1] = b0.y; b[2] = b0.z; b[3] = b0.w;
            b[4] = b1.x; b[5] = b1.y; b[6] = b1.z; b[7] = b1.w;
            #pragma unroll
            for (int i = 0; i < 8; i++)
                #pragma unroll
                for (int j = 0; j < 8; j++) acc[i][j] = fmaf(a[i], b[j], acc[i][j]);
        }
        __syncthreads();
    }

    float bv[8];
    #pragma unroll
    for (int j = 0; j < 8; j++) bv[j] = blockIdx.y ? bias[tx * 8 + j] : 0.0f;

    #pragma unroll
    for (int i = 0; i < 8; i++) {
        int gm = m0 + ty + 16 * i;
        if (gm < N_NODES) {
            float4 o0, o1;
            o0.x = acc[i][0] + bv[0]; o0.y = acc[i][1] + bv[1];
            o0.z = acc[i][2] + bv[2]; o0.w = acc[i][3] + bv[3];
            o1.x = acc[i][4] + bv[4]; o1.y = acc[i][5] + bv[5];
            o1.z = acc[i][6] + bv[6]; o1.w = acc[i][7] + bv[7];
            *(float4*)&out[(size_t)gm * CH + tx * 8]     = o0;
            *(float4*)&out[(size_t)gm * CH + tx * 8 + 4] = o1;
        }
    }
}

// ---------------- aggregation + root-term + relu ----------------
// warp per node; 128 ch = float4 per lane. res = relu(inv_deg * sum_nbr(tl) + tr)
// use_out: 0 -> write g_h, 1 -> write outext (d_out)
__global__ void __launch_bounds__(256)
agg_relu_kernel(float4* __restrict__ outext, int use_out) {
    const float4* tl = (const float4*)g_tl;
    const float4* tr = (const float4*)g_tr;
    float4* out = use_out ? outext : (float4*)g_h;

    int warp = threadIdx.x >> 5;
    int lane = threadIdx.x & 31;
    int node = blockIdx.x * 8 + warp;
    if (node >= N_NODES) return;

    int beg = g_rowptr[node];
    int end = g_rowptr[node + 1];

    float4 a0 = make_float4(0.f, 0.f, 0.f, 0.f);
    float4 a1 = a0, a2 = a0, a3 = a0;

    int e = beg;
    for (; e + 4 <= end; e += 4) {
        int s0 = g_col[e];
        int s1 = g_col[e + 1];
        int s2 = g_col[e + 2];
        int s3 = g_col[e + 3];
        float4 v0 = tl[(size_t)s0 * 32 + lane];
        float4 v1 = tl[(size_t)s1 * 32 + lane];
        float4 v2 = tl[(size_t)s2 * 32 + lane];
        float4 v3 = tl[(size_t)s3 * 32 + lane];
        a0.x += v0.x; a0.y += v0.y; a0.z += v0.z; a0.w += v0.w;
        a1.x += v1.x; a1.y += v1.y; a1.z += v1.z; a1.w += v1.w;
        a2.x += v2.x; a2.y += v2.y; a2.z += v2.z; a2.w += v2.w;
        a3.x += v3.x; a3.y += v3.y; a3.z += v3.z; a3.w += v3.w;
    }
    for (; e < end; e++) {
        int s0 = g_col[e];
        float4 v0 = tl[(size_t)s0 * 32 + lane];
        a0.x += v0.x; a0.y += v0.y; a0.z += v0.z; a0.w += v0.w;
    }
    a0.x += a1.x + a2.x + a3.x;
    a0.y += a1.y + a2.y + a3.y;
    a0.z += a1.z + a2.z + a3.z;
    a0.w += a1.w + a2.w + a3.w;

    float id = g_inv[node];
    float4 r = tr[(size_t)node * 32 + lane];
    float4 o;
    o.x = fmaxf(fmaf(a0.x, id, r.x), 0.0f);
    o.y = fmaxf(fmaf(a0.y, id, r.y), 0.0f);
    o.z = fmaxf(fmaf(a0.z, id, r.z), 0.0f);
    o.w = fmaxf(fmaf(a0.w, id, r.w), 0.0f);
    out[(size_t)node * 32 + lane] = o;
}

// ---------------- launch: ONLY kernel launches, no other runtime APIs ----------------
extern "C" void kernel_launch(void* const* d_in, const int* in_sizes, int n_in,
                              void* d_out, int out_size) {
    const float* x   = (const float*)d_in[0];
    const void*  ei  = d_in[1];                // int32 or int64, detected on device
    const float* Wl1 = (const float*)d_in[2];
    const float* Wr1 = (const float*)d_in[3];
    const float* b1  = (const float*)d_in[4];
    const float* Wl2 = (const float*)d_in[5];
    const float* Wr2 = (const float*)d_in[6];
    const float* b2  = (const float*)d_in[7];
    float4* out = (float4*)d_out;

    // ---- CSR build (reused by both layers) ----
    detect_dtype_kernel<<<1, 32>>>((const int*)ei);
    zero_deg_kernel<<<(N_NODES + 255) / 256, 256>>>();
    count_deg_kernel<<<(N_EDGES + 255) / 256, 256>>>(ei);
    scan_blocks_kernel<<<SCAN_BLOCKS, SCAN_BS>>>();
    scan_partials_kernel<<<1, 32>>>();
    finalize_kernel<<<SCAN_BLOCKS, SCAN_BS>>>();
    fill_csr_kernel<<<(N_EDGES + 255) / 256, 256>>>(ei);

    dim3 ggrid((N_NODES + 127) / 128, 2);

    // ---- layer 1 ----
    gemm_dual_kernel<<<ggrid, 256>>>(x, 0, Wl1, Wr1, b1);
    agg_relu_kernel<<<(N_NODES + 7) / 8, 256>>>(out, 0);
    // ---- layer 2 ----
    gemm_dual_kernel<<<ggrid, 256>>>(x, 1, Wl2, Wr2, b2);
    agg_relu_kernel<<<(N_NODES + 7) / 8, 256>>>(out, 1);
}

// round 7
// speedup vs baseline: 1.1969x; 1.1969x over previous
#include <cuda_runtime.h>
#include <cuda_bf16.h>

#define N_NODES 100000
#define N_EDGES 1600000
#define CH 128
#define SCAN_BS 1024
#define SCAN_BLOCKS 98   // ceil(100000/1024)

// ---------------- scratch (device globals; referenced ONLY from device code) ----------------
__device__ int   g_is64;                      // 1 if edge_index is int64, 0 if int32
__device__ int   g_deg[N_NODES];              // degree, then reused as CSR fill cursor
__device__ float g_inv[N_NODES];
__device__ int   g_rowptr[N_NODES + 1];
__device__ int   g_bsum[SCAN_BLOCKS + 1];
__device__ int   g_col[N_EDGES];              // src sorted by dst (CSR adjacency)
__device__ float g_tl[(size_t)N_NODES * CH];  // A @ Wl
__device__ float g_tr[(size_t)N_NODES * CH];  // A @ Wr + b
__device__ float g_h [(size_t)N_NODES * CH];  // hidden layer output

// ---------------- dtype detection ----------------
__global__ void detect_dtype_kernel(const int* __restrict__ ei32) {
    if (threadIdx.x == 0) {
        int odd_nonzero = 0;
        for (int i = 0; i < 128; i++)
            if (ei32[2 * i + 1] != 0) odd_nonzero++;
        g_is64 = (odd_nonzero == 0) ? 1 : 0;
    }
}

__device__ __forceinline__ int edge_at(const void* ei, long long idx) {
    if (g_is64) return (int)((const long long*)ei)[idx];
    return ((const int*)ei)[idx];
}

// ---------------- zero degree array ----------------
__global__ void zero_deg_kernel() {
    int i = blockIdx.x * 256 + threadIdx.x;
    if (i < N_NODES) g_deg[i] = 0;
}

// ---------------- degree histogram ----------------
__global__ void count_deg_kernel(const void* __restrict__ ei) {
    int e = blockIdx.x * 256 + threadIdx.x;
    if (e < N_EDGES) {
        int d = edge_at(ei, (long long)N_EDGES + e);
        atomicAdd(&g_deg[d], 1);
    }
}

// ---------------- block-local exclusive scan ----------------
__global__ void scan_blocks_kernel() {
    __shared__ int s[SCAN_BS];
    int tid = threadIdx.x;
    int i = blockIdx.x * SCAN_BS + tid;
    int v = (i < N_NODES) ? g_deg[i] : 0;
    s[tid] = v;
    __syncthreads();
    #pragma unroll
    for (int off = 1; off < SCAN_BS; off <<= 1) {
        int x = 0;
        if (tid >= off) x = s[tid - off];
        __syncthreads();
        s[tid] += x;
        __syncthreads();
    }
    if (i < N_NODES) g_rowptr[i] = s[tid] - v;
    if (tid == SCAN_BS - 1) g_bsum[blockIdx.x] = s[SCAN_BS - 1];
}

__global__ void scan_partials_kernel() {
    if (threadIdx.x == 0) {
        int acc = 0;
        for (int b = 0; b < SCAN_BLOCKS; b++) { int t = g_bsum[b]; g_bsum[b] = acc; acc += t; }
    }
}

__global__ void finalize_kernel() {
    int i = blockIdx.x * SCAN_BS + threadIdx.x;
    if (i < N_NODES) {
        int r = g_rowptr[i] + g_bsum[blockIdx.x];
        g_rowptr[i] = r;
        int d = g_deg[i];
        g_inv[i] = 1.0f / (d > 0 ? (float)d : 1.0f);
        g_deg[i] = r;
    }
    if (i == 0) g_rowptr[N_NODES] = N_EDGES;
}

// ---------------- CSR fill ----------------
__global__ void fill_csr_kernel(const void* __restrict__ ei) {
    int e = blockIdx.x * 256 + threadIdx.x;
    if (e < N_EDGES) {
        int s = edge_at(ei, e);
        int d = edge_at(ei, (long long)N_EDGES + e);
        int p = atomicAdd(&g_deg[d], 1);
        g_col[p] = s;
    }
}

// ---------------- tensor-core dual GEMM (bf16 3-term split) ----------------
// C = A@W in fp32-like precision: A=Ah+Al, W=Wh+Wl (bf16 each),
// C ~= Ah@Wh + Al@Wh + Ah@Wl  (dropped Al@Wl ~ 2^-18 rel).
// Block: 256 thr (8 warps), tile M=128 N=128, K chunked by 32.
// Warp grid 4(M) x 2(N): warp tile 32 x 64 -> 2 x 8 m16n8 tiles.
// blockIdx.y: 0 -> (Wl, g_tl), 1 -> (Wr, g_tr, +bias)

__device__ __forceinline__ unsigned pack2(float a, float b) {
    __nv_bfloat162 t = __floats2bfloat162_rn(a, b);
    return *(unsigned*)&t;
}

#define MMA_BF16(d, a, b) \
    asm volatile("mma.sync.aligned.m16n8k16.row.col.f32.bf16.bf16.f32 " \
                 "{%0,%1,%2,%3}, {%4,%5,%6,%7}, {%8,%9}, {%0,%1,%2,%3};" \
                 : "+f"(d[0]), "+f"(d[1]), "+f"(d[2]), "+f"(d[3]) \
                 : "r"(a[0]), "r"(a[1]), "r"(a[2]), "r"(a[3]), "r"(b[0]), "r"(b[1]))

__global__ void __launch_bounds__(256, 1)
gemm_dual_kernel(const float* __restrict__ Aext, int use_h,
                 const float* __restrict__ Wl, const float* __restrict__ Wr,
                 const float* __restrict__ bias) {
    const float* A  = use_h ? g_h : Aext;
    const float* W  = blockIdx.y ? Wr   : Wl;
    float*      out = blockIdx.y ? g_tr : g_tl;

    // sA row stride 40 bf16 (80B): a-frag load banks (20g+c)%32 all-distinct.
    __shared__ __nv_bfloat16 sAh[128][40];
    __shared__ __nv_bfloat16 sAl[128][40];
    // sW: [n][k2] packed bf16x2 (k even in low half), stride 20 words:
    // load banks (20g+c)%32 distinct; store banks (k2+16*n4grp)%32 distinct.
    __shared__ unsigned sWh[128][20];
    __shared__ unsigned sWl[128][20];

    int tid  = threadIdx.x;
    int warp = tid >> 5;
    int lane = tid & 31;
    int g = lane >> 2;          // 0..7
    int c = lane & 3;           // 0..3
    int wm = warp >> 1;         // 0..3  (M)
    int wn = warp & 1;          // 0..1  (N)
    int m0 = blockIdx.x * 128;

    float acc[2][8][4];
    #pragma unroll
    for (int mt = 0; mt < 2; mt++)
        #pragma unroll
        for (int nt = 0; nt < 8; nt++)
            #pragma unroll
            for (int r = 0; r < 4; r++) acc[mt][nt][r] = 0.0f;

    for (int k0 = 0; k0 < CH; k0 += 32) {
        // ---- A chunk: 128 rows x 32 k. thread: row = tid>>1, 16 cols ----
        {
            int row = tid >> 1;
            int cb  = (tid & 1) * 16;
            int gm  = m0 + row;
            bool ok = (gm < N_NODES);
            #pragma unroll
            for (int q = 0; q < 4; q++) {
                float4 v = make_float4(0.f, 0.f, 0.f, 0.f);
                if (ok) v = *(const float4*)&A[(size_t)gm * CH + k0 + cb + q * 4];
                unsigned hx = pack2(__bfloat162float(__float2bfloat16_rn(v.x)) == v.x ? v.x : v.x, v.y); // placeholder avoided below
                // hi parts
                __nv_bfloat16 h0 = __float2bfloat16_rn(v.x);
                __nv_bfloat16 h1 = __float2bfloat16_rn(v.y);
                __nv_bfloat16 h2 = __float2bfloat16_rn(v.z);
                __nv_bfloat16 h3 = __float2bfloat16_rn(v.w);
                // lo residuals
                float l0 = v.x - __bfloat162float(h0);
                float l1 = v.y - __bfloat162float(h1);
                float l2 = v.z - __bfloat162float(h2);
                float l3 = v.w - __bfloat162float(h3);
                __nv_bfloat162 hp0; hp0.x = h0; hp0.y = h1;
                __nv_bfloat162 hp1; hp1.x = h2; hp1.y = h3;
                *(unsigned*)&sAh[row][cb + q * 4]     = *(unsigned*)&hp0;
                *(unsigned*)&sAh[row][cb + q * 4 + 2] = *(unsigned*)&hp1;
                *(unsigned*)&sAl[row][cb + q * 4]     = pack2(l0, l1);
                *(unsigned*)&sAl[row][cb + q * 4 + 2] = pack2(l2, l3);
                (void)hx;
            }
        }
        // ---- W chunk: 32 k-rows x 128 n, packed as k-pairs ----
        {
            #pragma unroll
            for (int it = 0; it < 2; it++) {
                int t  = tid + it * 256;         // 0..511
                int k2 = t & 15;                 // k pair index in chunk
                int n4 = t >> 4;                 // 0..31
                const float* w0 = &W[(size_t)(k0 + 2 * k2) * CH + n4 * 4];
                const float* w1 = &W[(size_t)(k0 + 2 * k2 + 1) * CH + n4 * 4];
                float4 a4 = *(const float4*)w0;
                float4 b4 = *(const float4*)w1;
                float wa[4] = {a4.x, a4.y, a4.z, a4.w};
                float wb[4] = {b4.x, b4.y, b4.z, b4.w};
                #pragma unroll
                for (int j = 0; j < 4; j++) {
                    __nv_bfloat16 ha = __float2bfloat16_rn(wa[j]);
                    __nv_bfloat16 hb = __float2bfloat16_rn(wb[j]);
                    float la = wa[j] - __bfloat162float(ha);
                    float lb = wb[j] - __bfloat162float(hb);
                    __nv_bfloat162 hp; hp.x = ha; hp.y = hb;   // low = k even
                    sWh[n4 * 4 + j][k2] = *(unsigned*)&hp;
                    sWl[n4 * 4 + j][k2] = pack2(la, lb);
                }
            }
        }
        __syncthreads();

        // ---- compute: 2 k16 steps ----
        #pragma unroll
        for (int s = 0; s < 2; s++) {
            unsigned ah[2][4], al[2][4], bh[8][2], bl[8][2];
            #pragma unroll
            for (int mt = 0; mt < 2; mt++) {
                int rb = wm * 32 + mt * 16;
                int cb = s * 16 + 2 * c;
                ah[mt][0] = *(unsigned*)&sAh[rb + g][cb];
                ah[mt][1] = *(unsigned*)&sAh[rb + g + 8][cb];
                ah[mt][2] = *(unsigned*)&sAh[rb + g][cb + 8];
                ah[mt][3] = *(unsigned*)&sAh[rb + g + 8][cb + 8];
                al[mt][0] = *(unsigned*)&sAl[rb + g][cb];
                al[mt][1] = *(unsigned*)&sAl[rb + g + 8][cb];
                al[mt][2] = *(unsigned*)&sAl[rb + g][cb + 8];
                al[mt][3] = *(unsigned*)&sAl[rb + g + 8][cb + 8];
            }
            #pragma unroll
            for (int nt = 0; nt < 8; nt++) {
                int nb = wn * 64 + nt * 8 + g;
                bh[nt][0] = sWh[nb][8 * s + c];
                bh[nt][1] = sWh[nb][8 * s + c + 4];
                bl[nt][0] = sWl[nb][8 * s + c];
                bl[nt][1] = sWl[nb][8 * s + c + 4];
            }
            #pragma unroll
            for (int mt = 0; mt < 2; mt++)
                #pragma unroll
                for (int nt = 0; nt < 8; nt++) {
                    MMA_BF16(acc[mt][nt], ah[mt], bh[nt]);
                    MMA_BF16(acc[mt][nt], al[mt], bh[nt]);
                    MMA_BF16(acc[mt][nt], ah[mt], bl[nt]);
                }
        }
        __syncthreads();
    }

    // ---- epilogue: d0=C[g][2c], d1=C[g][2c+1], d2=C[g+8][2c], d3=C[g+8][2c+1] ----
    int with_bias = blockIdx.y;
    #pragma unroll
    for (int nt = 0; nt < 8; nt++) {
        int nb = wn * 64 + nt * 8 + 2 * c;
        float2 bv = make_float2(0.f, 0.f);
        if (with_bias) bv = *(const float2*)&bias[nb];
        #pragma unroll
        for (int mt = 0; mt < 2; mt++) {
            int rb = wm * 32 + mt * 16;
            int gm0 = m0 + rb + g;
            int gm1 = gm0 + 8;
            if (gm0 < N_NODES) {
                float2 o = make_float2(acc[mt][nt][0] + bv.x, acc[mt][nt][1] + bv.y);
                *(float2*)&out[(size_t)gm0 * CH + nb] = o;
            }
            if (gm1 < N_NODES) {
                float2 o = make_float2(acc[mt][nt][2] + bv.x, acc[mt][nt][3] + bv.y);
                *(float2*)&out[(size_t)gm1 * CH + nb] = o;
            }
        }
    }
}

// ---------------- aggregation + root-term + relu ----------------
__global__ void __launch_bounds__(256)
agg_relu_kernel(float4* __restrict__ outext, int use_out) {
    const float4* tl = (const float4*)g_tl;
    const float4* tr = (const float4*)g_tr;
    float4* out = use_out ? outext : (float4*)g_h;

    int warp = threadIdx.x >> 5;
    int lane = threadIdx.x & 31;
    int node = blockIdx.x * 8 + warp;
    if (node >= N_NODES) return;

    int beg = g_rowptr[node];
    int end = g_rowptr[node + 1];

    float4 a0 = make_float4(0.f, 0.f, 0.f, 0.f);
    float4 a1 = a0, a2 = a0, a3 = a0;

    int e = beg;
    for (; e + 4 <= end; e += 4) {
        int s0 = g_col[e];
        int s1 = g_col[e + 1];
        int s2 = g_col[e + 2];
        int s3 = g_col[e + 3];
        float4 v0 = tl[(size_t)s0 * 32 + lane];
        float4 v1 = tl[(size_t)s1 * 32 + lane];
        float4 v2 = tl[(size_t)s2 * 32 + lane];
        float4 v3 = tl[(size_t)s3 * 32 + lane];
        a0.x += v0.x; a0.y += v0.y; a0.z += v0.z; a0.w += v0.w;
        a1.x += v1.x; a1.y += v1.y; a1.z += v1.z; a1.w += v1.w;
        a2.x += v2.x; a2.y += v2.y; a2.z += v2.z; a2.w += v2.w;
        a3.x += v3.x; a3.y += v3.y; a3.z += v3.z; a3.w += v3.w;
    }
    for (; e < end; e++) {
        int s0 = g_col[e];
        float4 v0 = tl[(size_t)s0 * 32 + lane];
        a0.x += v0.x; a0.y += v0.y; a0.z += v0.z; a0.w += v0.w;
    }
    a0.x += a1.x + a2.x + a3.x;
    a0.y += a1.y + a2.y + a3.y;
    a0.z += a1.z + a2.z + a3.z;
    a0.w += a1.w + a2.w + a3.w;

    float id = g_inv[node];
    float4 r = tr[(size_t)node * 32 + lane];
    float4 o;
    o.x = fmaxf(fmaf(a0.x, id, r.x), 0.0f);
    o.y = fmaxf(fmaf(a0.y, id, r.y), 0.0f);
    o.z = fmaxf(fmaf(a0.z, id, r.z), 0.0f);
    o.w = fmaxf(fmaf(a0.w, id, r.w), 0.0f);
    out[(size_t)node * 32 + lane] = o;
}

// ---------------- launch: ONLY kernel launches, no other runtime APIs ----------------
extern "C" void kernel_launch(void* const* d_in, const int* in_sizes, int n_in,
                              void* d_out, int out_size) {
    const float* x   = (const float*)d_in[0];
    const void*  ei  = d_in[1];                // int32 or int64, detected on device
    const float* Wl1 = (const float*)d_in[2];
    const float* Wr1 = (const float*)d_in[3];
    const float* b1  = (const float*)d_in[4];
    const float* Wl2 = (const float*)d_in[5];
    const float* Wr2 = (const float*)d_in[6];
    const float* b2  = (const float*)d_in[7];
    float4* out = (float4*)d_out;

    // ---- CSR build (reused by both layers) ----
    detect_dtype_kernel<<<1, 32>>>((const int*)ei);
    zero_deg_kernel<<<(N_NODES + 255) / 256, 256>>>();
    count_deg_kernel<<<(N_EDGES + 255) / 256, 256>>>(ei);
    scan_blocks_kernel<<<SCAN_BLOCKS, SCAN_BS>>>();
    scan_partials_kernel<<<1, 32>>>();
    finalize_kernel<<<SCAN_BLOCKS, SCAN_BS>>>();
    fill_csr_kernel<<<(N_EDGES + 255) / 256, 256>>>(ei);

    dim3 ggrid((N_NODES + 127) / 128, 2);

    // ---- layer 1 ----
    gemm_dual_kernel<<<ggrid, 256>>>(x, 0, Wl1, Wr1, b1);
    agg_relu_kernel<<<(N_NODES + 7) / 8, 256>>>(out, 0);
    // ---- layer 2 ----
    gemm_dual_kernel<<<ggrid, 256>>>(x, 1, Wl2, Wr2, b2);
    agg_relu_kernel<<<(N_NODES + 7) / 8, 256>>>(out, 1);
}

// round 9
// speedup vs baseline: 1.3504x; 1.1283x over previous
#include <cuda_runtime.h>
#include <cuda_bf16.h>

#define N_NODES 100000
#define N_EDGES 1600000
#define CH 128
#define KP 64              // k-pairs per row (CH/2)
#define SCAN_BS 1024
#define SCAN_BLOCKS 98     // ceil(100000/1024)

// ---------------- scratch (device globals; referenced ONLY from device code) ----------------
__device__ int   g_is64;
__device__ int   g_deg[N_NODES];
__device__ float g_inv[N_NODES];
__device__ int   g_rowptr[N_NODES + 1];
__device__ int   g_bsum[SCAN_BLOCKS + 1];
__device__ int   g_col[N_EDGES];
__device__ float g_tl[(size_t)N_NODES * CH];      // A @ Wl
__device__ float g_tr[(size_t)N_NODES * CH];      // A @ Wr + b
// pre-split bf16 operands, packed as bf16x2 k-pairs (low = even k)
__device__ unsigned g_ah[(size_t)N_NODES * KP];   // x hi
__device__ unsigned g_al[(size_t)N_NODES * KP];   // x lo residual
__device__ unsigned g_hh[(size_t)N_NODES * KP];   // hidden hi
__device__ unsigned g_hl[(size_t)N_NODES * KP];   // hidden lo
__device__ unsigned g_wh[4 * CH * KP];            // W packed [mat][n][k2] hi
__device__ unsigned g_wl[4 * CH * KP];            // W packed lo

// ---------------- helpers ----------------
__device__ __forceinline__ void split_pack(float a, float b, unsigned& hi, unsigned& lo) {
    __nv_bfloat16 ha = __float2bfloat16_rn(a);
    __nv_bfloat16 hb = __float2bfloat16_rn(b);
    float ra = a - __bfloat162float(ha);
    float rb = b - __bfloat162float(hb);
    __nv_bfloat162 hv; hv.x = ha; hv.y = hb;
    hi = *(unsigned*)&hv;
    __nv_bfloat162 lv = __floats2bfloat162_rn(ra, rb);
    lo = *(unsigned*)&lv;
}

// ---------------- dtype detection ----------------
__global__ void detect_dtype_kernel(const int* __restrict__ ei32) {
    if (threadIdx.x == 0) {
        int odd_nonzero = 0;
        for (int i = 0; i < 128; i++)
            if (ei32[2 * i + 1] != 0) odd_nonzero++;
        g_is64 = (odd_nonzero == 0) ? 1 : 0;
    }
}

__device__ __forceinline__ int edge_at(const void* ei, long long idx) {
    if (g_is64) return (int)((const long long*)ei)[idx];
    return ((const int*)ei)[idx];
}

// ---------------- CSR build ----------------
__global__ void zero_deg_kernel() {
    int i = blockIdx.x * 256 + threadIdx.x;
    if (i < N_NODES) g_deg[i] = 0;
}

__global__ void count_deg_kernel(const void* __restrict__ ei) {
    int e = blockIdx.x * 256 + threadIdx.x;
    if (e < N_EDGES) {
        int d = edge_at(ei, (long long)N_EDGES + e);
        atomicAdd(&g_deg[d], 1);
    }
}

__global__ void scan_blocks_kernel() {
    __shared__ int s[SCAN_BS];
    int tid = threadIdx.x;
    int i = blockIdx.x * SCAN_BS + tid;
    int v = (i < N_NODES) ? g_deg[i] : 0;
    s[tid] = v;
    __syncthreads();
    #pragma unroll
    for (int off = 1; off < SCAN_BS; off <<= 1) {
        int x = 0;
        if (tid >= off) x = s[tid - off];
        __syncthreads();
        s[tid] += x;
        __syncthreads();
    }
    if (i < N_NODES) g_rowptr[i] = s[tid] - v;
    if (tid == SCAN_BS - 1) g_bsum[blockIdx.x] = s[SCAN_BS - 1];
}

__global__ void scan_partials_kernel() {
    if (threadIdx.x == 0) {
        int acc = 0;
        for (int b = 0; b < SCAN_BLOCKS; b++) { int t = g_bsum[b]; g_bsum[b] = acc; acc += t; }
    }
}

__global__ void finalize_kernel() {
    int i = blockIdx.x * SCAN_BS + threadIdx.x;
    if (i < N_NODES) {
        int r = g_rowptr[i] + g_bsum[blockIdx.x];
        g_rowptr[i] = r;
        int d = g_deg[i];
        g_inv[i] = 1.0f / (d > 0 ? (float)d : 1.0f);
        g_deg[i] = r;
    }
    if (i == 0) g_rowptr[N_NODES] = N_EDGES;
}

__global__ void fill_csr_kernel(const void* __restrict__ ei) {
    int e = blockIdx.x * 256 + threadIdx.x;
    if (e < N_EDGES) {
        int s = edge_at(ei, e);
        int d = edge_at(ei, (long long)N_EDGES + e);
        int p = atomicAdd(&g_deg[d], 1);
        g_col[p] = s;
    }
}

// ---------------- one-shot W split: g_wh/g_wl[mat][n][k2] = pack(W[2k2][n], W[2k2+1][n]) ----------------
__global__ void convert_w_kernel(const float* __restrict__ Wl1, const float* __restrict__ Wr1,
                                 const float* __restrict__ Wl2, const float* __restrict__ Wr2) {
    int t = blockIdx.x * 256 + threadIdx.x;
    if (t >= 4 * CH * KP) return;
    int mat = t >> 13;          // / (128*64)
    int rem = t & 8191;
    int n  = rem >> 6;
    int k2 = rem & 63;
    const float* W = (mat == 0) ? Wl1 : (mat == 1) ? Wr1 : (mat == 2) ? Wl2 : Wr2;
    float w0 = W[(2 * k2) * CH + n];
    float w1 = W[(2 * k2 + 1) * CH + n];
    split_pack(w0, w1, g_wh[t], g_wl[t]);
}

// ---------------- one-shot x split: g_ah/g_al[row][k2] ----------------
__global__ void convert_x_kernel(const float* __restrict__ x) {
    long long t = (long long)blockIdx.x * 256 + threadIdx.x;
    if (t >= (long long)N_NODES * KP) return;
    int row = (int)(t >> 6);
    int k2  = (int)(t & 63);
    float2 v = *(const float2*)&x[(size_t)row * CH + 2 * k2];
    split_pack(v.x, v.y, g_ah[t], g_al[t]);
}

// ---------------- fused tensor-core dual GEMM ----------------
// g_tl = A@Wl ; g_tr = A@Wr + b.  A pre-split bf16 hi/lo (3-term split product).
// Block: 256 thr, tile M=128, N=128 per W; warp grid 4(M) x 2(N).
#define MMA_BF16(d, a, b) \
    asm volatile("mma.sync.aligned.m16n8k16.row.col.f32.bf16.bf16.f32 " \
                 "{%0,%1,%2,%3}, {%4,%5,%6,%7}, {%8,%9}, {%0,%1,%2,%3};" \
                 : "+f"(d[0]), "+f"(d[1]), "+f"(d[2]), "+f"(d[3]) \
                 : "r"(a[0]), "r"(a[1]), "r"(a[2]), "r"(a[3]), "r"(b[0]), "r"(b[1]))

__global__ void __launch_bounds__(256, 1)
gemm_fused_kernel(int layer, const float* __restrict__ bias) {
    const unsigned* Ah = layer ? g_hh : g_ah;
    const unsigned* Al = layer ? g_hl : g_al;
    const unsigned* WHbase = g_wh + (size_t)(layer * 2) * CH * KP;
    const unsigned* WLbase = g_wl + (size_t)(layer * 2) * CH * KP;

    // stride 20 words: frag-load banks (20*row + c) % 32 all-distinct per warp
    __shared__ unsigned sAh[128 * 20];
    __shared__ unsigned sAl[128 * 20];
    __shared__ unsigned sWh[128 * 20];
    __shared__ unsigned sWl[128 * 20];

    int tid  = threadIdx.x;
    int warp = tid >> 5;
    int lane = tid & 31;
    int g = lane >> 2;
    int c = lane & 3;
    int wm = warp >> 1;
    int wn = warp & 1;
    int m0 = blockIdx.x * 128;

    float acc[2][2][8][4];
    #pragma unroll
    for (int w = 0; w < 2; w++)
        #pragma unroll
        for (int mt = 0; mt < 2; mt++)
            #pragma unroll
            for (int nt = 0; nt < 8; nt++)
                #pragma unroll
                for (int r = 0; r < 4; r++) acc[w][mt][nt][r] = 0.0f;

    for (int kp0 = 0; kp0 < KP; kp0 += 16) {
        // ---- stage A chunk: 128 rows x 16 words (hi + lo) ----
        #pragma unroll
        for (int i = 0; i < 2; i++) {
            int idx = tid + i * 256;
            int row = idx >> 2;
            int q   = (idx & 3) * 4;
            int gm  = m0 + row;
            uint4 vh = make_uint4(0, 0, 0, 0), vl = make_uint4(0, 0, 0, 0);
            if (gm < N_NODES) {
                vh = *(const uint4*)&Ah[(size_t)gm * KP + kp0 + q];
                vl = *(const uint4*)&Al[(size_t)gm * KP + kp0 + q];
            }
            *(uint4*)&sAh[row * 20 + q] = vh;
            *(uint4*)&sAl[row * 20 + q] = vl;
        }

        #pragma unroll
        for (int w = 0; w < 2; w++) {
            const unsigned* WH = WHbase + (size_t)w * CH * KP;
            const unsigned* WL = WLbase + (size_t)w * CH * KP;
            // ---- stage W chunk ----
            #pragma unroll
            for (int i = 0; i < 2; i++) {
                int idx = tid + i * 256;
                int n = idx >> 2;
                int q = (idx & 3) * 4;
                *(uint4*)&sWh[n * 20 + q] = *(const uint4*)&WH[(size_t)n * KP + kp0 + q];
                *(uint4*)&sWl[n * 20 + q] = *(const uint4*)&WL[(size_t)n * KP + kp0 + q];
            }
            __syncthreads();

            #pragma unroll
            for (int s = 0; s < 2; s++) {
                int wc = s * 8 + c;
                unsigned ah[2][4], al[2][4];
                #pragma unroll
                for (int mt = 0; mt < 2; mt++) {
                    int rb = wm * 32 + mt * 16;
                    ah[mt][0] = sAh[(rb + g) * 20 + wc];
                    ah[mt][1] = sAh[(rb + g + 8) * 20 + wc];
                    ah[mt][2] = sAh[(rb + g) * 20 + wc + 4];
                    ah[mt][3] = sAh[(rb + g + 8) * 20 + wc + 4];
                    al[mt][0] = sAl[(rb + g) * 20 + wc];
                    al[mt][1] = sAl[(rb + g + 8) * 20 + wc];
                    al[mt][2] = sAl[(rb + g) * 20 + wc + 4];
                    al[mt][3] = sAl[(rb + g + 8) * 20 + wc + 4];
                }
                #pragma unroll
                for (int nt = 0; nt < 8; nt++) {
                    int nb = wn * 64 + nt * 8 + g;
                    unsigned bh[2], bl[2];
                    bh[0] = sWh[nb * 20 + wc];
                    bh[1] = sWh[nb * 20 + wc + 4];
                    bl[0] = sWl[nb * 20 + wc];
                    bl[1] = sWl[nb * 20 + wc + 4];
                    #pragma unroll
                    for (int mt = 0; mt < 2; mt++) {
                        MMA_BF16(acc[w][mt][nt], ah[mt], bh);
                        MMA_BF16(acc[w][mt][nt], al[mt], bh);
                        MMA_BF16(acc[w][mt][nt], ah[mt], bl);
                    }
                }
            }
            __syncthreads();
        }
    }

    // ---- epilogue ----
    #pragma unroll
    for (int w = 0; w < 2; w++) {
        float* out = w ? g_tr : g_tl;
        #pragma unroll
        for (int nt = 0; nt < 8; nt++) {
            int nb = wn * 64 + nt * 8 + 2 * c;
            float2 bv = make_float2(0.f, 0.f);
            if (w) bv = *(const float2*)&bias[nb];
            #pragma unroll
            for (int mt = 0; mt < 2; mt++) {
                int rb = wm * 32 + mt * 16;
                int gm0 = m0 + rb + g;
                int gm1 = gm0 + 8;
                if (gm0 < N_NODES) {
                    float2 o = make_float2(acc[w][mt][nt][0] + bv.x, acc[w][mt][nt][1] + bv.y);
                    *(float2*)&out[(size_t)gm0 * CH + nb] = o;
                }
                if (gm1 < N_NODES) {
                    float2 o = make_float2(acc[w][mt][nt][2] + bv.x, acc[w][mt][nt][3] + bv.y);
                    *(float2*)&out[(size_t)gm1 * CH + nb] = o;
                }
            }
        }
    }
}

// ---------------- aggregation + root-term + relu ----------------
// mode 0: write hidden as pre-split bf16 hi/lo (g_hh/g_hl)
// mode 1: write fp32 float4 to outext (d_out)
__global__ void __launch_bounds__(256)
agg_relu_kernel(float4* __restrict__ outext, int mode) {
    const float4* tl = (const float4*)g_tl;
    const float4* tr = (const float4*)g_tr;

    int warp = threadIdx.x >> 5;
    int lane = threadIdx.x & 31;
    int node = blockIdx.x * 8 + warp;
    if (node >= N_NODES) return;

    int beg = g_rowptr[node];
    int end = g_rowptr[node + 1];

    float4 a0 = make_float4(0.f, 0.f, 0.f, 0.f);
    float4 a1 = a0, a2 = a0, a3 = a0;

    int e = beg;
    for (; e + 4 <= end; e += 4) {
        int s0 = g_col[e];
        int s1 = g_col[e + 1];
        int s2 = g_col[e + 2];
        int s3 = g_col[e + 3];
        float4 v0 = tl[(size_t)s0 * 32 + lane];
        float4 v1 = tl[(size_t)s1 * 32 + lane];
        float4 v2 = tl[(size_t)s2 * 32 + lane];
        float4 v3 = tl[(size_t)s3 * 32 + lane];
        a0.x += v0.x; a0.y += v0.y; a0.z += v0.z; a0.w += v0.w;
        a1.x += v1.x; a1.y += v1.y; a1.z += v1.z; a1.w += v1.w;
        a2.x += v2.x; a2.y += v2.y; a2.z += v2.z; a2.w += v2.w;
        a3.x += v3.x; a3.y += v3.y; a3.z += v3.z; a3.w += v3.w;
    }
    for (; e < end; e++) {
        int s0 = g_col[e];
        float4 v0 = tl[(size_t)s0 * 32 + lane];
        a0.x += v0.x; a0.y += v0.y; a0.z += v0.z; a0.w += v0.w;
    }
    a0.x += a1.x + a2.x + a3.x;
    a0.y += a1.y + a2.y + a3.y;
    a0.z += a1.z + a2.z + a3.z;
    a0.w += a1.w + a2.w + a3.w;

    float id = g_inv[node];
    float4 r = tr[(size_t)node * 32 + lane];
    float4 o;
    o.x = fmaxf(fmaf(a0.x, id, r.x), 0.0f);
    o.y = fmaxf(fmaf(a0.y, id, r.y), 0.0f);
    o.z = fmaxf(fmaf(a0.z, id, r.z), 0.0f);
    o.w = fmaxf(fmaf(a0.w, id, r.w), 0.0f);

    if (mode) {
        outext[(size_t)node * 32 + lane] = o;
    } else {
        uint2 vh, vl;
        split_pack(o.x, o.y, vh.x, vl.x);
        split_pack(o.z, o.w, vh.y, vl.y);
        size_t base = (size_t)node * KP + 2 * lane;
        *(uint2*)&g_hh[base] = vh;
        *(uint2*)&g_hl[base] = vl;
    }
}

// ---------------- launch: ONLY kernel launches ----------------
extern "C" void kernel_launch(void* const* d_in, const int* in_sizes, int n_in,
                              void* d_out, int out_size) {
    const float* x   = (const float*)d_in[0];
    const void*  ei  = d_in[1];
    const float* Wl1 = (const float*)d_in[2];
    const float* Wr1 = (const float*)d_in[3];
    const float* b1  = (const float*)d_in[4];
    const float* Wl2 = (const float*)d_in[5];
    const float* Wr2 = (const float*)d_in[6];
    const float* b2  = (const float*)d_in[7];
    float4* out = (float4*)d_out;

    // ---- CSR build ----
    detect_dtype_kernel<<<1, 32>>>((const int*)ei);
    zero_deg_kernel<<<(N_NODES + 255) / 256, 256>>>();
    count_deg_kernel<<<(N_EDGES + 255) / 256, 256>>>(ei);
    scan_blocks_kernel<<<SCAN_BLOCKS, SCAN_BS>>>();
    scan_partials_kernel<<<1, 32>>>();
    finalize_kernel<<<SCAN_BLOCKS, SCAN_BS>>>();
    fill_csr_kernel<<<(N_EDGES + 255) / 256, 256>>>(ei);

    // ---- operand pre-split ----
    convert_w_kernel<<<(4 * CH * KP + 255) / 256, 256>>>(Wl1, Wr1, Wl2, Wr2);
    convert_x_kernel<<<(int)(((long long)N_NODES * KP + 255) / 256), 256>>>(x);

    // ---- layer 1 ----
    gemm_fused_kernel<<<(N_NODES + 127) / 128, 256>>>(0, b1);
    agg_relu_kernel<<<(N_NODES + 7) / 8, 256>>>(out, 0);
    // ---- layer 2 ----
    gemm_fused_kernel<<<(N_NODES + 127) / 128, 256>>>(1, b2);
    agg_relu_kernel<<<(N_NODES + 7) / 8, 256>>>(out, 1);
}

// round 11
// speedup vs baseline: 1.4012x; 1.0376x over previous
#include <cuda_runtime.h>
#include <cuda_bf16.h>

#define N_NODES 100000
#define N_EDGES 1600000
#define CH 128
#define KP 64              // k-pairs per row (CH/2)
#define SCAN_BS 1024
#define SCAN_BLOCKS 98     // ceil(100000/1024)

// ---------------- scratch (device globals; referenced ONLY from device code) ----------------
__device__ int   g_is64;
__device__ int   g_deg[N_NODES];
__device__ float g_inv[N_NODES];
__device__ int   g_rowptr[N_NODES + 1];
__device__ int   g_bsum[SCAN_BLOCKS + 1];
__device__ int   g_col[N_EDGES];
__device__ float g_tl[(size_t)N_NODES * CH];      // A @ Wl
__device__ float g_tr[(size_t)N_NODES * CH];      // A @ Wr + b
// pre-split bf16 operands, packed as bf16x2 k-pairs (low = even k)
__device__ unsigned g_ah[(size_t)N_NODES * KP];   // x hi
__device__ unsigned g_al[(size_t)N_NODES * KP];   // x lo residual
__device__ unsigned g_hh[(size_t)N_NODES * KP];   // hidden hi
__device__ unsigned g_hl[(size_t)N_NODES * KP];   // hidden lo
__device__ unsigned g_wh[4 * CH * KP];            // W packed [mat][n][k2] hi
__device__ unsigned g_wl[4 * CH * KP];            // W packed lo

// ---------------- helpers ----------------
__device__ __forceinline__ void split_pack(float a, float b, unsigned& hi, unsigned& lo) {
    __nv_bfloat16 ha = __float2bfloat16_rn(a);
    __nv_bfloat16 hb = __float2bfloat16_rn(b);
    float ra = a - __bfloat162float(ha);
    float rb = b - __bfloat162float(hb);
    __nv_bfloat162 hv; hv.x = ha; hv.y = hb;
    hi = *(unsigned*)&hv;
    __nv_bfloat162 lv = __floats2bfloat162_rn(ra, rb);
    lo = *(unsigned*)&lv;
}

__device__ __forceinline__ unsigned smem_u32(const void* p) {
    return (unsigned)__cvta_generic_to_shared(p);
}

#define LDMX4(r0, r1, r2, r3, addr) \
    asm volatile("ldmatrix.sync.aligned.m8n8.x4.shared.b16 {%0,%1,%2,%3}, [%4];" \
                 : "=r"(r0), "=r"(r1), "=r"(r2), "=r"(r3) : "r"(addr))

#define MMA_BF16(d, a, b) \
    asm volatile("mma.sync.aligned.m16n8k16.row.col.f32.bf16.bf16.f32 " \
                 "{%0,%1,%2,%3}, {%4,%5,%6,%7}, {%8,%9}, {%0,%1,%2,%3};" \
                 : "+f"(d[0]), "+f"(d[1]), "+f"(d[2]), "+f"(d[3]) \
                 : "r"(a[0]), "r"(a[1]), "r"(a[2]), "r"(a[3]), "r"(b[0]), "r"(b[1]))

// ---------------- dtype detection (128 threads, or-reduce) ----------------
__global__ void detect_dtype_kernel(const int* __restrict__ ei32) {
    int v = ei32[2 * threadIdx.x + 1];
    int cnt = __syncthreads_count(v != 0);
    if (threadIdx.x == 0) g_is64 = (cnt == 0) ? 1 : 0;
}

__device__ __forceinline__ int edge_at(const void* ei, long long idx) {
    if (g_is64) return (int)((const long long*)ei)[idx];
    return ((const int*)ei)[idx];
}

// ---------------- CSR build ----------------
__global__ void zero_deg_kernel() {
    int i = blockIdx.x * 256 + threadIdx.x;
    if (i < N_NODES) g_deg[i] = 0;
}

__global__ void count_deg_kernel(const void* __restrict__ ei) {
    int e = blockIdx.x * 256 + threadIdx.x;
    if (e < N_EDGES) {
        int d = edge_at(ei, (long long)N_EDGES + e);
        atomicAdd(&g_deg[d], 1);
    }
}

__global__ void scan_blocks_kernel() {
    __shared__ int s[SCAN_BS];
    int tid = threadIdx.x;
    int i = blockIdx.x * SCAN_BS + tid;
    int v = (i < N_NODES) ? g_deg[i] : 0;
    s[tid] = v;
    __syncthreads();
    #pragma unroll
    for (int off = 1; off < SCAN_BS; off <<= 1) {
        int x = 0;
        if (tid >= off) x = s[tid - off];
        __syncthreads();
        s[tid] += x;
        __syncthreads();
    }
    if (i < N_NODES) g_rowptr[i] = s[tid] - v;
    if (tid == SCAN_BS - 1) g_bsum[blockIdx.x] = s[SCAN_BS - 1];
}

// 128-thread block scan over 98 partials (replaces 1-thread serial chain)
__global__ void scan_partials_kernel() {
    __shared__ int s[128];
    int tid = threadIdx.x;
    int v = (tid < SCAN_BLOCKS) ? g_bsum[tid] : 0;
    s[tid] = v;
    __syncthreads();
    #pragma unroll
    for (int off = 1; off < 128; off <<= 1) {
        int x = 0;
        if (tid >= off) x = s[tid - off];
        __syncthreads();
        s[tid] += x;
        __syncthreads();
    }
    if (tid < SCAN_BLOCKS) g_bsum[tid] = s[tid] - v;   // exclusive
}

__global__ void finalize_kernel() {
    int i = blockIdx.x * SCAN_BS + threadIdx.x;
    if (i < N_NODES) {
        int r = g_rowptr[i] + g_bsum[blockIdx.x];
        g_rowptr[i] = r;
        int d = g_deg[i];
        g_inv[i] = 1.0f / (d > 0 ? (float)d : 1.0f);
        g_deg[i] = r;
    }
    if (i == 0) g_rowptr[N_NODES] = N_EDGES;
}

__global__ void fill_csr_kernel(const void* __restrict__ ei) {
    int e = blockIdx.x * 256 + threadIdx.x;
    if (e < N_EDGES) {
        int s = edge_at(ei, e);
        int d = edge_at(ei, (long long)N_EDGES + e);
        int p = atomicAdd(&g_deg[d], 1);
        g_col[p] = s;
    }
}

// ---------------- one-shot W split ----------------
__global__ void convert_w_kernel(const float* __restrict__ Wl1, const float* __restrict__ Wr1,
                                 const float* __restrict__ Wl2, const float* __restrict__ Wr2) {
    int t = blockIdx.x * 256 + threadIdx.x;
    if (t >= 4 * CH * KP) return;
    int mat = t >> 13;
    int rem = t & 8191;
    int n  = rem >> 6;
    int k2 = rem & 63;
    const float* W = (mat == 0) ? Wl1 : (mat == 1) ? Wr1 : (mat == 2) ? Wl2 : Wr2;
    float w0 = W[(2 * k2) * CH + n];
    float w1 = W[(2 * k2 + 1) * CH + n];
    split_pack(w0, w1, g_wh[t], g_wl[t]);
}

// ---------------- one-shot x split ----------------
__global__ void convert_x_kernel(const float* __restrict__ x) {
    long long t = (long long)blockIdx.x * 256 + threadIdx.x;
    if (t >= (long long)N_NODES * KP) return;
    int row = (int)(t >> 6);
    int k2  = (int)(t & 63);
    float2 v = *(const float2*)&x[(size_t)row * CH + 2 * k2];
    split_pack(v.x, v.y, g_ah[t], g_al[t]);
}

// ---------------- fused tensor-core dual GEMM (ldmatrix frag loads) ----------------
// g_tl = A@Wl ; g_tr = A@Wr + b. 3-term bf16 split. Block 256 thr, tile M=128.
// Warp grid 4(M) x 2(N). Stride 20 words: ldmatrix 8-row phases hit banks
// (20r mod 32) = {0,20,8,28,16,4,24,12} — conflict-free.
__global__ void __launch_bounds__(256, 1)
gemm_fused_kernel(int layer, const float* __restrict__ bias) {
    const unsigned* Ah = layer ? g_hh : g_ah;
    const unsigned* Al = layer ? g_hl : g_al;
    const unsigned* WHbase = g_wh + (size_t)(layer * 2) * CH * KP;
    const unsigned* WLbase = g_wl + (size_t)(layer * 2) * CH * KP;

    __shared__ unsigned sAh[128 * 20];
    __shared__ unsigned sAl[128 * 20];
    __shared__ unsigned sWh[128 * 20];
    __shared__ unsigned sWl[128 * 20];

    int tid  = threadIdx.x;
    int warp = tid >> 5;
    int lane = tid & 31;
    int c = lane & 3;
    int g = lane >> 2;
    int wm = warp >> 1;
    int wn = warp & 1;
    int m0 = blockIdx.x * 128;

    float acc[2][2][8][4];
    #pragma unroll
    for (int w = 0; w < 2; w++)
        #pragma unroll
        for (int mt = 0; mt < 2; mt++)
            #pragma unroll
            for (int nt = 0; nt < 8; nt++)
                #pragma unroll
                for (int r = 0; r < 4; r++) acc[w][mt][nt][r] = 0.0f;

    // ldmatrix source addresses (constant over chunks modulo the colw offset)
    int arow  = (lane & 15);            // row within 16-row A tile
    int acolq = (lane >> 4) * 4;        // +0 / +4 words (k2 halves 0..7 / 8..15)
    int brow  = (lane & 7) + ((lane >> 4) << 3);   // n row within 16-row tile-pair
    int bcolq = ((lane >> 3) & 1) * 4;  // +0 / +4 words

    for (int kp0 = 0; kp0 < KP; kp0 += 16) {
        // ---- stage A chunk: 128 rows x 16 words (hi + lo) ----
        #pragma unroll
        for (int i = 0; i < 2; i++) {
            int idx = tid + i * 256;
            int row = idx >> 2;
            int q   = (idx & 3) * 4;
            int gm  = m0 + row;
            uint4 vh = make_uint4(0, 0, 0, 0), vl = make_uint4(0, 0, 0, 0);
            if (gm < N_NODES) {
                vh = *(const uint4*)&Ah[(size_t)gm * KP + kp0 + q];
                vl = *(const uint4*)&Al[(size_t)gm * KP + kp0 + q];
            }
            *(uint4*)&sAh[row * 20 + q] = vh;
            *(uint4*)&sAl[row * 20 + q] = vl;
        }
        // ---- stage W(w=0) chunk ----
        {
            const unsigned* WH = WHbase;
            const unsigned* WL = WLbase;
            #pragma unroll
            for (int i = 0; i < 2; i++) {
                int idx = tid + i * 256;
                int n = idx >> 2;
                int q = (idx & 3) * 4;
                *(uint4*)&sWh[n * 20 + q] = *(const uint4*)&WH[(size_t)n * KP + kp0 + q];
                *(uint4*)&sWl[n * 20 + q] = *(const uint4*)&WL[(size_t)n * KP + kp0 + q];
            }
        }
        __syncthreads();

        // ---- A fragments via ldmatrix.x4, shared by both W matrices ----
        unsigned ah[2][2][4], al[2][2][4];   // [mt][s]
        #pragma unroll
        for (int mt = 0; mt < 2; mt++)
            #pragma unroll
            for (int s = 0; s < 2; s++) {
                int off = (wm * 32 + mt * 16 + arow) * 20 + s * 8 + acolq;
                LDMX4(ah[mt][s][0], ah[mt][s][1], ah[mt][s][2], ah[mt][s][3],
                      smem_u32(&sAh[off]));
                LDMX4(al[mt][s][0], al[mt][s][1], al[mt][s][2], al[mt][s][3],
                      smem_u32(&sAl[off]));
            }

        #pragma unroll
        for (int w = 0; w < 2; w++) {
            if (w == 1) {
                __syncthreads();   // all reads of W(w=0) done
                const unsigned* WH = WHbase + (size_t)CH * KP;
                const unsigned* WL = WLbase + (size_t)CH * KP;
                #pragma unroll
                for (int i = 0; i < 2; i++) {
                    int idx = tid + i * 256;
                    int n = idx >> 2;
                    int q = (idx & 3) * 4;
                    *(uint4*)&sWh[n * 20 + q] = *(const uint4*)&WH[(size_t)n * KP + kp0 + q];
                    *(uint4*)&sWl[n * 20 + q] = *(const uint4*)&WL[(size_t)n * KP + kp0 + q];
                }
                __syncthreads();
            }

            #pragma unroll
            for (int s = 0; s < 2; s++)
                #pragma unroll
                for (int ntp = 0; ntp < 4; ntp++) {
                    int off = (wn * 64 + ntp * 16 + brow) * 20 + s * 8 + bcolq;
                    unsigned bh[4], bl[4];
                    LDMX4(bh[0], bh[1], bh[2], bh[3], smem_u32(&sWh[off]));
                    LDMX4(bl[0], bl[1], bl[2], bl[3], smem_u32(&sWl[off]));
                    #pragma unroll
                    for (int mt = 0; mt < 2; mt++) {
                        MMA_BF16(acc[w][mt][2 * ntp],     ah[mt][s], (bh + 0));
                        MMA_BF16(acc[w][mt][2 * ntp],     al[mt][s], (bh + 0));
                        MMA_BF16(acc[w][mt][2 * ntp],     ah[mt][s], (bl + 0));
                        MMA_BF16(acc[w][mt][2 * ntp + 1], ah[mt][s], (bh + 2));
                        MMA_BF16(acc[w][mt][2 * ntp + 1], al[mt][s], (bh + 2));
                        MMA_BF16(acc[w][mt][2 * ntp + 1], ah[mt][s], (bl + 2));
                    }
                }
        }
        __syncthreads();
    }

    // ---- epilogue ----
    #pragma unroll
    for (int w = 0; w < 2; w++) {
        float* out = w ? g_tr : g_tl;
        #pragma unroll
        for (int nt = 0; nt < 8; nt++) {
            int nb = wn * 64 + nt * 8 + 2 * c;
            float2 bv = make_float2(0.f, 0.f);
            if (w) bv = *(const float2*)&bias[nb];
            #pragma unroll
            for (int mt = 0; mt < 2; mt++) {
                int rb = wm * 32 + mt * 16;
                int gm0 = m0 + rb + g;
                int gm1 = gm0 + 8;
                if (gm0 < N_NODES) {
                    float2 o = make_float2(acc[w][mt][nt][0] + bv.x, acc[w][mt][nt][1] + bv.y);
                    *(float2*)&out[(size_t)gm0 * CH + nb] = o;
                }
                if (gm1 < N_NODES) {
                    float2 o = make_float2(acc[w][mt][nt][2] + bv.x, acc[w][mt][nt][3] + bv.y);
                    *(float2*)&out[(size_t)gm1 * CH + nb] = o;
                }
            }
        }
    }
}

// ---------------- aggregation + root-term + relu ----------------
__global__ void __launch_bounds__(256)
agg_relu_kernel(float4* __restrict__ outext, int mode) {
    const float4* tl = (const float4*)g_tl;
    const float4* tr = (const float4*)g_tr;

    int warp = threadIdx.x >> 5;
    int lane = threadIdx.x & 31;
    int node = blockIdx.x * 8 + warp;
    if (node >= N_NODES) return;

    int beg = g_rowptr[node];
    int end = g_rowptr[node + 1];

    float4 a0 = make_float4(0.f, 0.f, 0.f, 0.f);
    float4 a1 = a0, a2 = a0, a3 = a0;

    int e = beg;
    for (; e + 4 <= end; e += 4) {
        int s0 = g_col[e];
        int s1 = g_col[e + 1];
        int s2 = g_col[e + 2];
        int s3 = g_col[e + 3];
        float4 v0 = tl[(size_t)s0 * 32 + lane];
        float4 v1 = tl[(size_t)s1 * 32 + lane];
        float4 v2 = tl[(size_t)s2 * 32 + lane];
        float4 v3 = tl[(size_t)s3 * 32 + lane];
        a0.x += v0.x; a0.y += v0.y; a0.z += v0.z; a0.w += v0.w;
        a1.x += v1.x; a1.y += v1.y; a1.z += v1.z; a1.w += v1.w;
        a2.x += v2.x; a2.y += v2.y; a2.z += v2.z; a2.w += v2.w;
        a3.x += v3.x; a3.y += v3.y; a3.z += v3.z; a3.w += v3.w;
    }
    for (; e < end; e++) {
        int s0 = g_col[e];
        float4 v0 = tl[(size_t)s0 * 32 + lane];
        a0.x += v0.x; a0.y += v0.y; a0.z += v0.z; a0.w += v0.w;
    }
    a0.x += a1.x + a2.x + a3.x;
    a0.y += a1.y + a2.y + a3.y;
    a0.z += a1.z + a2.z + a3.z;
    a0.w += a1.w + a2.w + a3.w;

    float id = g_inv[node];
    float4 r = tr[(size_t)node * 32 + lane];
    float4 o;
    o.x = fmaxf(fmaf(a0.x, id, r.x), 0.0f);
    o.y = fmaxf(fmaf(a0.y, id, r.y), 0.0f);
    o.z = fmaxf(fmaf(a0.z, id, r.z), 0.0f);
    o.w = fmaxf(fmaf(a0.w, id, r.w), 0.0f);

    if (mode) {
        outext[(size_t)node * 32 + lane] = o;
    } else {
        uint2 vh, vl;
        split_pack(o.x, o.y, vh.x, vl.x);
        split_pack(o.z, o.w, vh.y, vl.y);
        size_t base = (size_t)node * KP + 2 * lane;
        *(uint2*)&g_hh[base] = vh;
        *(uint2*)&g_hl[base] = vl;
    }
}

// ---------------- launch: ONLY kernel launches ----------------
extern "C" void kernel_launch(void* const* d_in, const int* in_sizes, int n_in,
                              void* d_out, int out_size) {
    const float* x   = (const float*)d_in[0];
    const void*  ei  = d_in[1];
    const float* Wl1 = (const float*)d_in[2];
    const float* Wr1 = (const float*)d_in[3];
    const float* b1  = (const float*)d_in[4];
    const float* Wl2 = (const float*)d_in[5];
    const float* Wr2 = (const float*)d_in[6];
    const float* b2  = (const float*)d_in[7];
    float4* out = (float4*)d_out;

    // ---- CSR build ----
    detect_dtype_kernel<<<1, 128>>>((const int*)ei);
    zero_deg_kernel<<<(N_NODES + 255) / 256, 256>>>();
    count_deg_kernel<<<(N_EDGES + 255) / 256, 256>>>(ei);
    scan_blocks_kernel<<<SCAN_BLOCKS, SCAN_BS>>>();
    scan_partials_kernel<<<1, 128>>>();
    finalize_kernel<<<SCAN_BLOCKS, SCAN_BS>>>();
    fill_csr_kernel<<<(N_EDGES + 255) / 256, 256>>>(ei);

    // ---- operand pre-split ----
    convert_w_kernel<<<(4 * CH * KP + 255) / 256, 256>>>(Wl1, Wr1, Wl2, Wr2);
    convert_x_kernel<<<(int)(((long long)N_NODES * KP + 255) / 256), 256>>>(x);

    // ---- layer 1 ----
    gemm_fused_kernel<<<(N_NODES + 127) / 128, 256>>>(0, b1);
    agg_relu_kernel<<<(N_NODES + 7) / 8, 256>>>(out, 0);
    // ---- layer 2 ----
    gemm_fused_kernel<<<(N_NODES + 127) / 128, 256>>>(1, b2);
    agg_relu_kernel<<<(N_NODES + 7) / 8, 256>>>(out, 1);
}

// round 15
// speedup vs baseline: 1.4720x; 1.0506x over previous
#include <cuda_runtime.h>
#include <cuda_bf16.h>
#include <cuda_fp16.h>

#define N_NODES 100000
#define N_EDGES 1600000
#define CH 128
#define KP 64              // k-pairs per row (CH/2)
#define SCAN_BS 1024
#define SCAN_BLOCKS 98     // ceil(100000/1024)

// ---------------- scratch (device globals; referenced ONLY from device code) ----------------
__device__ int    g_is64;
__device__ int    g_deg[N_NODES];
__device__ float  g_inv[N_NODES];
__device__ int    g_rowptr[N_NODES + 1];
__device__ int    g_bsum[SCAN_BLOCKS + 1];
__device__ int    g_col[N_EDGES];
__device__ __half g_tl[(size_t)N_NODES * CH];     // A @ Wl  (fp16: halves agg gather traffic)
__device__ float  g_tr[(size_t)N_NODES * CH];     // A @ Wr + b (fp32: root term accuracy)
// pre-split bf16 operands, packed as bf16x2 k-pairs (low = even k)
__device__ unsigned g_ah[(size_t)N_NODES * KP];   // x hi
__device__ unsigned g_al[(size_t)N_NODES * KP];   // x lo residual
__device__ unsigned g_hh[(size_t)N_NODES * KP];   // hidden hi
__device__ unsigned g_hl[(size_t)N_NODES * KP];   // hidden lo
__device__ unsigned g_wh[4 * CH * KP];            // W packed [mat][n][k2] hi
__device__ unsigned g_wl[4 * CH * KP];            // W packed lo

// ---------------- helpers ----------------
__device__ __forceinline__ void split_pack(float a, float b, unsigned& hi, unsigned& lo) {
    __nv_bfloat16 ha = __float2bfloat16_rn(a);
    __nv_bfloat16 hb = __float2bfloat16_rn(b);
    float ra = a - __bfloat162float(ha);
    float rb = b - __bfloat162float(hb);
    __nv_bfloat162 hv; hv.x = ha; hv.y = hb;
    hi = *(unsigned*)&hv;
    __nv_bfloat162 lv = __floats2bfloat162_rn(ra, rb);
    lo = *(unsigned*)&lv;
}

__device__ __forceinline__ unsigned smem_u32(const void* p) {
    return (unsigned)__cvta_generic_to_shared(p);
}

#define LDMX4(r0, r1, r2, r3, addr) \
    asm volatile("ldmatrix.sync.aligned.m8n8.x4.shared.b16 {%0,%1,%2,%3}, [%4];" \
                 : "=r"(r0), "=r"(r1), "=r"(r2), "=r"(r3) : "r"(addr))

#define MMA_BF16(d, a, b) \
    asm volatile("mma.sync.aligned.m16n8k16.row.col.f32.bf16.bf16.f32 " \
                 "{%0,%1,%2,%3}, {%4,%5,%6,%7}, {%8,%9}, {%0,%1,%2,%3};" \
                 : "+f"(d[0]), "+f"(d[1]), "+f"(d[2]), "+f"(d[3]) \
                 : "r"(a[0]), "r"(a[1]), "r"(a[2]), "r"(a[3]), "r"(b[0]), "r"(b[1]))

// ---------------- dtype detection (128 threads, or-reduce) ----------------
__global__ void detect_dtype_kernel(const int* __restrict__ ei32) {
    int v = ei32[2 * threadIdx.x + 1];
    int cnt = __syncthreads_count(v != 0);
    if (threadIdx.x == 0) g_is64 = (cnt == 0) ? 1 : 0;
}

__device__ __forceinline__ int edge_at(const void* ei, long long idx) {
    if (g_is64) return (int)((const long long*)ei)[idx];
    return ((const int*)ei)[idx];
}

// ---------------- CSR build ----------------
__global__ void zero_deg_kernel() {
    int i = blockIdx.x * 256 + threadIdx.x;
    if (i < N_NODES) g_deg[i] = 0;
}

__global__ void count_deg_kernel(const void* __restrict__ ei) {
    int e = blockIdx.x * 256 + threadIdx.x;
    if (e < N_EDGES) {
        int d = edge_at(ei, (long long)N_EDGES + e);
        atomicAdd(&g_deg[d], 1);
    }
}

__global__ void scan_blocks_kernel() {
    __shared__ int s[SCAN_BS];
    int tid = threadIdx.x;
    int i = blockIdx.x * SCAN_BS + tid;
    int v = (i < N_NODES) ? g_deg[i] : 0;
    s[tid] = v;
    __syncthreads();
    #pragma unroll
    for (int off = 1; off < SCAN_BS; off <<= 1) {
        int x = 0;
        if (tid >= off) x = s[tid - off];
        __syncthreads();
        s[tid] += x;
        __syncthreads();
    }
    if (i < N_NODES) g_rowptr[i] = s[tid] - v;
    if (tid == SCAN_BS - 1) g_bsum[blockIdx.x] = s[SCAN_BS - 1];
}

__global__ void scan_partials_kernel() {
    __shared__ int s[128];
    int tid = threadIdx.x;
    int v = (tid < SCAN_BLOCKS) ? g_bsum[tid] : 0;
    s[tid] = v;
    __syncthreads();
    #pragma unroll
    for (int off = 1; off < 128; off <<= 1) {
        int x = 0;
        if (tid >= off) x = s[tid - off];
        __syncthreads();
        s[tid] += x;
        __syncthreads();
    }
    if (tid < SCAN_BLOCKS) g_bsum[tid] = s[tid] - v;   // exclusive
}

__global__ void finalize_kernel() {
    int i = blockIdx.x * SCAN_BS + threadIdx.x;
    if (i < N_NODES) {
        int r = g_rowptr[i] + g_bsum[blockIdx.x];
        g_rowptr[i] = r;
        int d = g_deg[i];
        g_inv[i] = 1.0f / (d > 0 ? (float)d : 1.0f);
        g_deg[i] = r;
    }
    if (i == 0) g_rowptr[N_NODES] = N_EDGES;
}

__global__ void fill_csr_kernel(const void* __restrict__ ei) {
    int e = blockIdx.x * 256 + threadIdx.x;
    if (e < N_EDGES) {
        int s = edge_at(ei, e);
        int d = edge_at(ei, (long long)N_EDGES + e);
        int p = atomicAdd(&g_deg[d], 1);
        g_col[p] = s;
    }
}

// ---------------- one-shot W split ----------------
__global__ void convert_w_kernel(const float* __restrict__ Wl1, const float* __restrict__ Wr1,
                                 const float* __restrict__ Wl2, const float* __restrict__ Wr2) {
    int t = blockIdx.x * 256 + threadIdx.x;
    if (t >= 4 * CH * KP) return;
    int mat = t >> 13;
    int rem = t & 8191;
    int n  = rem >> 6;
    int k2 = rem & 63;
    const float* W = (mat == 0) ? Wl1 : (mat == 1) ? Wr1 : (mat == 2) ? Wl2 : Wr2;
    float w0 = W[(2 * k2) * CH + n];
    float w1 = W[(2 * k2 + 1) * CH + n];
    split_pack(w0, w1, g_wh[t], g_wl[t]);
}

// ---------------- one-shot x split ----------------
__global__ void convert_x_kernel(const float* __restrict__ x) {
    long long t = (long long)blockIdx.x * 256 + threadIdx.x;
    if (t >= (long long)N_NODES * KP) return;
    int row = (int)(t >> 6);
    int k2  = (int)(t & 63);
    float2 v = *(const float2*)&x[(size_t)row * CH + 2 * k2];
    split_pack(v.x, v.y, g_ah[t], g_al[t]);
}

// ---------------- fused tensor-core dual GEMM (ldmatrix frag loads) ----------------
// g_tl(fp16) = A@Wl ; g_tr(fp32) = A@Wr + b. 3-term bf16 split.
__global__ void __launch_bounds__(256, 1)
gemm_fused_kernel(int layer, const float* __restrict__ bias) {
    const unsigned* Ah = layer ? g_hh : g_ah;
    const unsigned* Al = layer ? g_hl : g_al;
    const unsigned* WHbase = g_wh + (size_t)(layer * 2) * CH * KP;
    const unsigned* WLbase = g_wl + (size_t)(layer * 2) * CH * KP;

    __shared__ unsigned sAh[128 * 20];
    __shared__ unsigned sAl[128 * 20];
    __shared__ unsigned sWh[128 * 20];
    __shared__ unsigned sWl[128 * 20];

    int tid  = threadIdx.x;
    int warp = tid >> 5;
    int lane = tid & 31;
    int c = lane & 3;
    int g = lane >> 2;
    int wm = warp >> 1;
    int wn = warp & 1;
    int m0 = blockIdx.x * 128;

    float acc[2][2][8][4];
    #pragma unroll
    for (int w = 0; w < 2; w++)
        #pragma unroll
        for (int mt = 0; mt < 2; mt++)
            #pragma unroll
            for (int nt = 0; nt < 8; nt++)
                #pragma unroll
                for (int r = 0; r < 4; r++) acc[w][mt][nt][r] = 0.0f;

    int arow  = (lane & 15);
    int acolq = (lane >> 4) * 4;
    int brow  = (lane & 7) + ((lane >> 4) << 3);
    int bcolq = ((lane >> 3) & 1) * 4;

    for (int kp0 = 0; kp0 < KP; kp0 += 16) {
        #pragma unroll
        for (int i = 0; i < 2; i++) {
            int idx = tid + i * 256;
            int row = idx >> 2;
            int q   = (idx & 3) * 4;
            int gm  = m0 + row;
            uint4 vh = make_uint4(0, 0, 0, 0), vl = make_uint4(0, 0, 0, 0);
            if (gm < N_NODES) {
                vh = *(const uint4*)&Ah[(size_t)gm * KP + kp0 + q];
                vl = *(const uint4*)&Al[(size_t)gm * KP + kp0 + q];
            }
            *(uint4*)&sAh[row * 20 + q] = vh;
            *(uint4*)&sAl[row * 20 + q] = vl;
        }
        {
            const unsigned* WH = WHbase;
            const unsigned* WL = WLbase;
            #pragma unroll
            for (int i = 0; i < 2; i++) {
                int idx = tid + i * 256;
                int n = idx >> 2;
                int q = (idx & 3) * 4;
                *(uint4*)&sWh[n * 20 + q] = *(const uint4*)&WH[(size_t)n * KP + kp0 + q];
                *(uint4*)&sWl[n * 20 + q] = *(const uint4*)&WL[(size_t)n * KP + kp0 + q];
            }
        }
        __syncthreads();

        unsigned ah[2][2][4], al[2][2][4];
        #pragma unroll
        for (int mt = 0; mt < 2; mt++)
            #pragma unroll
            for (int s = 0; s < 2; s++) {
                int off = (wm * 32 + mt * 16 + arow) * 20 + s * 8 + acolq;
                LDMX4(ah[mt][s][0], ah[mt][s][1], ah[mt][s][2], ah[mt][s][3],
                      smem_u32(&sAh[off]));
                LDMX4(al[mt][s][0], al[mt][s][1], al[mt][s][2], al[mt][s][3],
                      smem_u32(&sAl[off]));
            }

        #pragma unroll
        for (int w = 0; w < 2; w++) {
            if (w == 1) {
                __syncthreads();
                const unsigned* WH = WHbase + (size_t)CH * KP;
                const unsigned* WL = WLbase + (size_t)CH * KP;
                #pragma unroll
                for (int i = 0; i < 2; i++) {
                    int idx = tid + i * 256;
                    int n = idx >> 2;
                    int q = (idx & 3) * 4;
                    *(uint4*)&sWh[n * 20 + q] = *(const uint4*)&WH[(size_t)n * KP + kp0 + q];
                    *(uint4*)&sWl[n * 20 + q] = *(const uint4*)&WL[(size_t)n * KP + kp0 + q];
                }
                __syncthreads();
            }

            #pragma unroll
            for (int s = 0; s < 2; s++)
                #pragma unroll
                for (int ntp = 0; ntp < 4; ntp++) {
                    int off = (wn * 64 + ntp * 16 + brow) * 20 + s * 8 + bcolq;
                    unsigned bh[4], bl[4];
                    LDMX4(bh[0], bh[1], bh[2], bh[3], smem_u32(&sWh[off]));
                    LDMX4(bl[0], bl[1], bl[2], bl[3], smem_u32(&sWl[off]));
                    #pragma unroll
                    for (int mt = 0; mt < 2; mt++) {
                        MMA_BF16(acc[w][mt][2 * ntp],     ah[mt][s], (bh + 0));
                        MMA_BF16(acc[w][mt][2 * ntp],     al[mt][s], (bh + 0));
                        MMA_BF16(acc[w][mt][2 * ntp],     ah[mt][s], (bl + 0));
                        MMA_BF16(acc[w][mt][2 * ntp + 1], ah[mt][s], (bh + 2));
                        MMA_BF16(acc[w][mt][2 * ntp + 1], al[mt][s], (bh + 2));
                        MMA_BF16(acc[w][mt][2 * ntp + 1], ah[mt][s], (bl + 2));
                    }
                }
        }
        __syncthreads();
    }

    // ---- epilogue: w=0 -> fp16 g_tl, w=1 -> fp32 g_tr + bias ----
    #pragma unroll
    for (int nt = 0; nt < 8; nt++) {
        int nb = wn * 64 + nt * 8 + 2 * c;
        // w = 0 (tl, fp16)
        #pragma unroll
        for (int mt = 0; mt < 2; mt++) {
            int rb = wm * 32 + mt * 16;
            int gm0 = m0 + rb + g;
            int gm1 = gm0 + 8;
            if (gm0 < N_NODES)
                *(__half2*)&g_tl[(size_t)gm0 * CH + nb] =
                    __floats2half2_rn(acc[0][mt][nt][0], acc[0][mt][nt][1]);
            if (gm1 < N_NODES)
                *(__half2*)&g_tl[(size_t)gm1 * CH + nb] =
                    __floats2half2_rn(acc[0][mt][nt][2], acc[0][mt][nt][3]);
        }
        // w = 1 (tr, fp32 + bias)
        float2 bv = *(const float2*)&bias[nb];
        #pragma unroll
        for (int mt = 0; mt < 2; mt++) {
            int rb = wm * 32 + mt * 16;
            int gm0 = m0 + rb + g;
            int gm1 = gm0 + 8;
            if (gm0 < N_NODES) {
                float2 o = make_float2(acc[1][mt][nt][0] + bv.x, acc[1][mt][nt][1] + bv.y);
                *(float2*)&g_tr[(size_t)gm0 * CH + nb] = o;
            }
            if (gm1 < N_NODES) {
                float2 o = make_float2(acc[1][mt][nt][2] + bv.x, acc[1][mt][nt][3] + bv.y);
                *(float2*)&g_tr[(size_t)gm1 * CH + nb] = o;
            }
        }
    }
}

// ---------------- aggregation + root-term + relu ----------------
// tl rows are fp16 (8B per lane = 4 ch). fp32 accumulation.
// mode 0: write hidden as pre-split bf16 hi/lo; mode 1: write fp32 d_out
__global__ void __launch_bounds__(256)
agg_relu_kernel(float4* __restrict__ outext, int mode) {
    const float4* tr = (const float4*)g_tr;

    int warp = threadIdx.x >> 5;
    int lane = threadIdx.x & 31;
    int node = blockIdx.x * 8 + warp;
    if (node >= N_NODES) return;

    int beg = g_rowptr[node];
    int end = g_rowptr[node + 1];

    float4 a0 = make_float4(0.f, 0.f, 0.f, 0.f);
    float4 a1 = a0, a2 = a0, a3 = a0;

    int e = beg;
    for (; e + 4 <= end; e += 4) {
        int s0 = g_col[e];
        int s1 = g_col[e + 1];
        int s2 = g_col[e + 2];
        int s3 = g_col[e + 3];
        uint2 r0 = *(const uint2*)&g_tl[(size_t)s0 * CH + 4 * lane];
        uint2 r1 = *(const uint2*)&g_tl[(size_t)s1 * CH + 4 * lane];
        uint2 r2 = *(const uint2*)&g_tl[(size_t)s2 * CH + 4 * lane];
        uint2 r3 = *(const uint2*)&g_tl[(size_t)s3 * CH + 4 * lane];
        float2 p;
        p = __half22float2(*(__half2*)&r0.x); a0.x += p.x; a0.y += p.y;
        p = __half22float2(*(__half2*)&r0.y); a0.z += p.x; a0.w += p.y;
        p = __half22float2(*(__half2*)&r1.x); a1.x += p.x; a1.y += p.y;
        p = __half22float2(*(__half2*)&r1.y); a1.z += p.x; a1.w += p.y;
        p = __half22float2(*(__half2*)&r2.x); a2.x += p.x; a2.y += p.y;
        p = __half22float2(*(__half2*)&r2.y); a2.z += p.x; a2.w += p.y;
        p = __half22float2(*(__half2*)&r3.x); a3.x += p.x; a3.y += p.y;
        p = __half22float2(*(__half2*)&r3.y); a3.z += p.x; a3.w += p.y;
    }
    for (; e < end; e++) {
        int s0 = g_col[e];
        uint2 r0 = *(const uint2*)&g_tl[(size_t)s0 * CH + 4 * lane];
        float2 p;
        p = __half22float2(*(__half2*)&r0.x); a0.x += p.x; a0.y += p.y;
        p = __half22float2(*(__half2*)&r0.y); a0.z += p.x; a0.w += p.y;
    }
    a0.x += a1.x + a2.x + a3.x;
    a0.y += a1.y + a2.y + a3.y;
    a0.z += a1.z + a2.z + a3.z;
    a0.w += a1.w + a2.w + a3.w;

    float id = g_inv[node];
    float4 r = tr[(size_t)node * 32 + lane];
    float4 o;
    o.x = fmaxf(fmaf(a0.x, id, r.x), 0.0f);
    o.y = fmaxf(fmaf(a0.y, id, r.y), 0.0f);
    o.z = fmaxf(fmaf(a0.z, id, r.z), 0.0f);
    o.w = fmaxf(fmaf(a0.w, id, r.w), 0.0f);

    if (mode) {
        outext[(size_t)node * 32 + lane] = o;
    } else {
        uint2 vh, vl;
        split_pack(o.x, o.y, vh.x, vl.x);
        split_pack(o.z, o.w, vh.y, vl.y);
        size_t base = (size_t)node * KP + 2 * lane;
        *(uint2*)&g_hh[base] = vh;
        *(uint2*)&g_hl[base] = vl;
    }
}

// ---------------- launch: ONLY kernel launches ----------------
// Order puts gemm_fused at launch #6 so ncu (-s 5 -c 1) profiles the GEMM.
extern "C" void kernel_launch(void* const* d_in, const int* in_sizes, int n_in,
                              void* d_out, int out_size) {
    const float* x   = (const float*)d_in[0];
    const void*  ei  = d_in[1];
    const float* Wl1 = (const float*)d_in[2];
    const float* Wr1 = (const float*)d_in[3];
    const float* b1  = (const float*)d_in[4];
    const float* Wl2 = (const float*)d_in[5];
    const float* Wr2 = (const float*)d_in[6];
    const float* b2  = (const float*)d_in[7];
    float4* out = (float4*)d_out;

    // 1-5: independent prep
    detect_dtype_kernel<<<1, 128>>>((const int*)ei);
    zero_deg_kernel<<<(N_NODES + 255) / 256, 256>>>();
    count_deg_kernel<<<(N_EDGES + 255) / 256, 256>>>(ei);
    convert_w_kernel<<<(4 * CH * KP + 255) / 256, 256>>>(Wl1, Wr1, Wl2, Wr2);
    convert_x_kernel<<<(int)(((long long)N_NODES * KP + 255) / 256), 256>>>(x);

    // 6: layer-1 GEMM (profiled by ncu)
    gemm_fused_kernel<<<(N_NODES + 127) / 128, 256>>>(0, b1);

    // 7-10: finish CSR build (needed only by agg)
    scan_blocks_kernel<<<SCAN_BLOCKS, SCAN_BS>>>();
    scan_partials_kernel<<<1, 128>>>();
    finalize_kernel<<<SCAN_BLOCKS, SCAN_BS>>>();
    fill_csr_kernel<<<(N_EDGES + 255) / 256, 256>>>(ei);

    // 11: layer-1 aggregation
    agg_relu_kernel<<<(N_NODES + 7) / 8, 256>>>(out, 0);
    // 12-13: layer 2
    gemm_fused_kernel<<<(N_NODES + 127) / 128, 256>>>(1, b2);
    agg_relu_kernel<<<(N_NODES + 7) / 8, 256>>>(out, 1);
}